// round 5
// baseline (speedup 1.0000x reference)
#include <cuda_runtime.h>

#define NN 2000
#define NE 40000
#define NB 4
#define NT 34
#define TP 32
#define BT 128          // NB * TP
#define NC 32           // channels (C_IN == DC == 32)
#define MAXDEG 256

// ---------------- device scratch (static, no runtime alloc) ----------------
__device__ float d_hw[NN * BT * NC];     // (n, bt, ch) — node-major, 16KB/node
__device__ float d_deg[NN];
__device__ float d_dis[NN];
__device__ float d_selfnorm[NN];
__device__ int   d_cnt[NN];
__device__ int   d_start[NN + 1];
__device__ int   d_cursor[NN];
__device__ int   d_src[NE];
__device__ float d_cnorm[NE];
__device__ int   d_is64;                 // edge_index stored as int64?

__device__ __forceinline__ int edge_at(const int* __restrict__ ei, int idx) {
    return d_is64 ? ei[2 * idx] : ei[idx];
}

// ---------------- setup 1: dtype detect + init ----------------
__global__ void k_setup1(const int* __restrict__ ei) {
    int n = blockIdx.x * blockDim.x + threadIdx.x;
    if (n < NN) { d_deg[n] = 1.0f; d_cnt[n] = 0; }   // self-loop weight = 1
    if (blockIdx.x == 0 && threadIdx.x < 32) {
        // int64 little-endian node ids < 2000 => every odd 32-bit word is 0.
        int lane = threadIdx.x;
        int nz = 0;
        for (int i = lane; i < 128; i += 32)
            if (ei[2 * i + 1] != 0) nz = 1;
        unsigned any = __ballot_sync(0xffffffffu, nz);
        if (lane == 0) d_is64 = (any == 0u) ? 1 : 0;
    }
}

__global__ void k_count(const int* __restrict__ ei,
                        const float* __restrict__ ew) {
    int e = blockIdx.x * blockDim.x + threadIdx.x;
    if (e < NE) {
        int col = edge_at(ei, NE + e);
        atomicAdd(&d_deg[col], ew[e]);
        atomicAdd(&d_cnt[col], 1);
    }
}

// scan over d_cnt -> d_start/d_cursor; also deg -> dis/selfnorm (fused)
__global__ void k_scan() {
    __shared__ int sh[1024];
    int t = threadIdx.x;
    int i0 = 2 * t, i1 = 2 * t + 1;
    if (i0 < NN) { float r = rsqrtf(d_deg[i0]); d_dis[i0] = r; d_selfnorm[i0] = r * r; }
    if (i1 < NN) { float r = rsqrtf(d_deg[i1]); d_dis[i1] = r; d_selfnorm[i1] = r * r; }
    int a = (i0 < NN) ? d_cnt[i0] : 0;
    int b = (i1 < NN) ? d_cnt[i1] : 0;
    int s = a + b;
    sh[t] = s;
    __syncthreads();
    for (int off = 1; off < 1024; off <<= 1) {
        int v = (t >= off) ? sh[t - off] : 0;
        __syncthreads();
        sh[t] += v;
        __syncthreads();
    }
    int excl = sh[t] - s;
    if (i0 < NN) { d_start[i0] = excl;     d_cursor[i0] = excl; }
    if (i1 < NN) { d_start[i1] = excl + a; d_cursor[i1] = excl + a; }
    if (t == 1023) d_start[NN] = sh[1023];
}

__global__ void k_fill(const int* __restrict__ ei,
                       const float* __restrict__ ew) {
    int e = blockIdx.x * blockDim.x + threadIdx.x;
    if (e < NE) {
        int row = edge_at(ei, e);
        int col = edge_at(ei, NE + e);
        float nw = d_dis[row] * ew[e] * d_dis[col];
        int pos = atomicAdd(&d_cursor[col], 1);
        d_src[pos]   = row;
        d_cnorm[pos] = nw;
    }
}

// ---------------- gate conv + tanh*sigmoid + gcn_w GEMM ----------------
// one warp per (bt, n); lane = channel. writes (n, bt, ch) layout.
__global__ void __launch_bounds__(256) k_gate(
    const float* __restrict__ x,
    const float* __restrict__ g1w, const float* __restrict__ g1b,
    const float* __restrict__ g2w, const float* __restrict__ g2b,
    const float* __restrict__ gw)
{
    __shared__ float4 wpack[32][32];   // [c][dc] = (w1a, w1b, w2a, w2b)
    __shared__ float  gsh[32][32];     // [dc][ch]
    int tid = threadIdx.x;
    for (int i = tid; i < 1024; i += 256) {
        int dc = i & 31, c = i >> 5;
        wpack[c][dc] = make_float4(g1w[dc * 64 + c * 2], g1w[dc * 64 + c * 2 + 1],
                                   g2w[dc * 64 + c * 2], g2w[dc * 64 + c * 2 + 1]);
        gsh[i >> 5][i & 31] = gw[i];   // gw[dc*32 + ch]
    }
    __syncthreads();

    int lane = tid & 31, wid = tid >> 5;
    float b1 = g1b[lane], b2 = g2b[lane];
    int nwarps = gridDim.x * 8;

    for (int task = blockIdx.x * 8 + wid; task < BT * NN; task += nwarps) {
        int bt = task / NN;
        int n  = task - bt * NN;
        int b  = bt >> 5, t = bt & 31;
        const float* xp = x + (((size_t)b * NT + t) * NN + n) * NC;
        float x0 = xp[lane];
        float x1 = xp[2 * NN * NC + lane];

        float acc1 = b1, acc2 = b2;
        #pragma unroll
        for (int c = 0; c < 32; ++c) {
            float v0 = __shfl_sync(0xffffffffu, x0, c);
            float v1 = __shfl_sync(0xffffffffu, x1, c);
            float4 w = wpack[c][lane];
            acc1 = fmaf(v0, w.x, acc1);
            acc1 = fmaf(v1, w.y, acc1);
            acc2 = fmaf(v0, w.z, acc2);
            acc2 = fmaf(v1, w.w, acc2);
        }
        float h = tanhf(acc1) * (1.0f / (1.0f + expf(-acc2)));

        float acc = 0.0f;
        #pragma unroll
        for (int dc = 0; dc < 32; ++dc) {
            float hv = __shfl_sync(0xffffffffu, h, dc);
            acc = fmaf(hv, gsh[dc][lane], acc);
        }
        d_hw[((size_t)n * BT + bt) * NC + lane] = acc;   // node-major
    }
}

// ---------------- CSR gather: one block per node, all 128 bt in registers ----------------
// thread tid owns flats {4*tid + k*1024, +1..3}, flat = bt*32 + ch
__global__ void __launch_bounds__(256) k_gather(
    const float* __restrict__ gb, float* __restrict__ out)
{
    __shared__ int   s_src[MAXDEG];
    __shared__ float s_nrm[MAXDEG];
    int n   = blockIdx.x;
    int tid = threadIdx.x;

    const float4* own = (const float4*)(d_hw + (size_t)n * (BT * NC));
    float sn = d_selfnorm[n];
    float4 a0 = own[tid      ];
    float4 a1 = own[tid + 256];
    float4 a2 = own[tid + 512];
    float4 a3 = own[tid + 768];
    a0.x *= sn; a0.y *= sn; a0.z *= sn; a0.w *= sn;
    a1.x *= sn; a1.y *= sn; a1.z *= sn; a1.w *= sn;
    a2.x *= sn; a2.y *= sn; a2.z *= sn; a2.w *= sn;
    a3.x *= sn; a3.y *= sn; a3.z *= sn; a3.w *= sn;

    int s = d_start[n], e = d_start[n + 1];
    for (int base = s; base < e; base += MAXDEG) {
        int cnt = min(e - base, MAXDEG);
        __syncthreads();
        if (tid < cnt) { s_src[tid] = d_src[base + tid]; s_nrm[tid] = d_cnorm[base + tid]; }
        __syncthreads();
        for (int j = 0; j < cnt; ++j) {
            const float4* sv = (const float4*)(d_hw + (size_t)s_src[j] * (BT * NC));
            float w = s_nrm[j];
            float4 b0 = sv[tid      ];
            float4 b1 = sv[tid + 256];
            float4 b2 = sv[tid + 512];
            float4 b3 = sv[tid + 768];
            a0.x = fmaf(w, b0.x, a0.x); a0.y = fmaf(w, b0.y, a0.y);
            a0.z = fmaf(w, b0.z, a0.z); a0.w = fmaf(w, b0.w, a0.w);
            a1.x = fmaf(w, b1.x, a1.x); a1.y = fmaf(w, b1.y, a1.y);
            a1.z = fmaf(w, b1.z, a1.z); a1.w = fmaf(w, b1.w, a1.w);
            a2.x = fmaf(w, b2.x, a2.x); a2.y = fmaf(w, b2.y, a2.y);
            a2.z = fmaf(w, b2.z, a2.z); a2.w = fmaf(w, b2.w, a2.w);
            a3.x = fmaf(w, b3.x, a3.x); a3.y = fmaf(w, b3.y, a3.y);
            a3.z = fmaf(w, b3.z, a3.z); a3.w = fmaf(w, b3.w, a3.w);
        }
    }

    // out layout (bt, n, ch). flat = 4*tid + k*1024 -> bt = tid>>3 + 32k, ch = (4*tid)&31
    float4 bv = ((const float4*)gb)[tid & 7];
    int bt0 = tid >> 3;
    int ch  = (4 * tid) & 31;
    a0.x += bv.x; a0.y += bv.y; a0.z += bv.z; a0.w += bv.w;
    a1.x += bv.x; a1.y += bv.y; a1.z += bv.z; a1.w += bv.w;
    a2.x += bv.x; a2.y += bv.y; a2.z += bv.z; a2.w += bv.w;
    a3.x += bv.x; a3.y += bv.y; a3.z += bv.z; a3.w += bv.w;
    *(float4*)(out + ((size_t)(bt0     ) * NN + n) * NC + ch) = a0;
    *(float4*)(out + ((size_t)(bt0 + 32) * NN + n) * NC + ch) = a1;
    *(float4*)(out + ((size_t)(bt0 + 64) * NN + n) * NC + ch) = a2;
    *(float4*)(out + ((size_t)(bt0 + 96) * NN + n) * NC + ch) = a3;
}

// ---------------- launch ----------------
extern "C" void kernel_launch(void* const* d_in, const int* in_sizes, int n_in,
                              void* d_out, int out_size)
{
    const float* x   = (const float*)d_in[0];
    const int*   ei  = (const int*)d_in[1];
    const float* ew  = (const float*)d_in[2];
    const float* g1w = (const float*)d_in[3];
    const float* g1b = (const float*)d_in[4];
    const float* g2w = (const float*)d_in[5];
    const float* g2b = (const float*)d_in[6];
    const float* gw  = (const float*)d_in[7];
    const float* gb  = (const float*)d_in[8];
    float* out = (float*)d_out;

    k_setup1<<<(NN + 255) / 256, 256>>>(ei);
    k_count<<<(NE + 255) / 256, 256>>>(ei, ew);
    k_scan<<<1, 1024>>>();
    k_fill<<<(NE + 255) / 256, 256>>>(ei, ew);
    k_gate<<<1184, 256>>>(x, g1w, g1b, g2w, g2b, gw);
    k_gather<<<NN, 256>>>(gb, out);
}

// round 6
// speedup vs baseline: 1.4526x; 1.4526x over previous
#include <cuda_runtime.h>

#define NN 2000
#define NE 40000
#define NB 4
#define NT 34
#define TP 32
#define BT 128          // NB * TP
#define NC 32           // channels (C_IN == DC == 32)

// ---------------- device scratch (static, no runtime alloc) ----------------
__device__ float d_hw[BT * NN * NC];     // (bt, n, ch)  bt-major (R3 layout)
__device__ float d_deg[NN];
__device__ float d_dis[NN];
__device__ float d_selfnorm[NN];
__device__ int   d_cnt[NN];
__device__ int   d_start[NN + 1];
__device__ int   d_cursor[NN];
__device__ int   d_src[NE];
__device__ float d_cnorm[NE];
__device__ int   d_is64;                 // edge_index stored as int64?

__device__ __forceinline__ int edge_at(const int* __restrict__ ei, int idx) {
    return d_is64 ? ei[2 * idx] : ei[idx];
}

// ---------------- setup: dtype detect + init ----------------
__global__ void k_setup1(const int* __restrict__ ei) {
    int n = blockIdx.x * blockDim.x + threadIdx.x;
    if (n < NN) { d_deg[n] = 1.0f; d_cnt[n] = 0; }   // self-loop weight = 1
    if (blockIdx.x == 0 && threadIdx.x < 32) {
        int lane = threadIdx.x;
        int nz = 0;
        for (int i = lane; i < 128; i += 32)
            if (ei[2 * i + 1] != 0) nz = 1;
        unsigned any = __ballot_sync(0xffffffffu, nz);
        if (lane == 0) d_is64 = (any == 0u) ? 1 : 0;
    }
}

__global__ void k_count(const int* __restrict__ ei,
                        const float* __restrict__ ew) {
    int e = blockIdx.x * blockDim.x + threadIdx.x;
    if (e < NE) {
        int col = edge_at(ei, NE + e);
        atomicAdd(&d_deg[col], ew[e]);
        atomicAdd(&d_cnt[col], 1);
    }
}

// scan over d_cnt -> d_start/d_cursor; also deg -> dis/selfnorm (fused)
__global__ void k_scan() {
    __shared__ int sh[1024];
    int t = threadIdx.x;
    int i0 = 2 * t, i1 = 2 * t + 1;
    if (i0 < NN) { float r = rsqrtf(d_deg[i0]); d_dis[i0] = r; d_selfnorm[i0] = r * r; }
    if (i1 < NN) { float r = rsqrtf(d_deg[i1]); d_dis[i1] = r; d_selfnorm[i1] = r * r; }
    int a = (i0 < NN) ? d_cnt[i0] : 0;
    int b = (i1 < NN) ? d_cnt[i1] : 0;
    int s = a + b;
    sh[t] = s;
    __syncthreads();
    for (int off = 1; off < 1024; off <<= 1) {
        int v = (t >= off) ? sh[t - off] : 0;
        __syncthreads();
        sh[t] += v;
        __syncthreads();
    }
    int excl = sh[t] - s;
    if (i0 < NN) { d_start[i0] = excl;     d_cursor[i0] = excl; }
    if (i1 < NN) { d_start[i1] = excl + a; d_cursor[i1] = excl + a; }
    if (t == 1023) d_start[NN] = sh[1023];
}

__global__ void k_fill(const int* __restrict__ ei,
                       const float* __restrict__ ew) {
    int e = blockIdx.x * blockDim.x + threadIdx.x;
    if (e < NE) {
        int row = edge_at(ei, e);
        int col = edge_at(ei, NE + e);
        float nw = d_dis[row] * ew[e] * d_dis[col];
        int pos = atomicAdd(&d_cursor[col], 1);
        d_src[pos]   = row;
        d_cnorm[pos] = nw;
    }
}

// ---------------- gate conv + tanh*sigmoid + gcn_w GEMM (R3 version) ----------------
// one warp per (bt, n); lane = channel. writes bt-major (bt, n, ch).
__global__ void __launch_bounds__(256) k_gate(
    const float* __restrict__ x,
    const float* __restrict__ g1w, const float* __restrict__ g1b,
    const float* __restrict__ g2w, const float* __restrict__ g2b,
    const float* __restrict__ gw)
{
    __shared__ float4 wpack[32][32];   // [c][dc] = (w1a, w1b, w2a, w2b)
    __shared__ float  gsh[32][32];     // [dc][ch]
    int tid = threadIdx.x;
    for (int i = tid; i < 1024; i += 256) {
        int dc = i & 31, c = i >> 5;
        wpack[c][dc] = make_float4(g1w[dc * 64 + c * 2], g1w[dc * 64 + c * 2 + 1],
                                   g2w[dc * 64 + c * 2], g2w[dc * 64 + c * 2 + 1]);
        gsh[i >> 5][i & 31] = gw[i];   // gw[dc*32 + ch]
    }
    __syncthreads();

    int lane = tid & 31, wid = tid >> 5;
    float b1 = g1b[lane], b2 = g2b[lane];
    int nwarps = gridDim.x * 8;

    for (int task = blockIdx.x * 8 + wid; task < BT * NN; task += nwarps) {
        int bt = task / NN;
        int n  = task - bt * NN;
        int b  = bt >> 5, t = bt & 31;
        const float* xp = x + (((size_t)b * NT + t) * NN + n) * NC;
        float x0 = xp[lane];
        float x1 = xp[2 * NN * NC + lane];

        float acc1 = b1, acc2 = b2;
        #pragma unroll
        for (int c = 0; c < 32; ++c) {
            float v0 = __shfl_sync(0xffffffffu, x0, c);
            float v1 = __shfl_sync(0xffffffffu, x1, c);
            float4 w = wpack[c][lane];
            acc1 = fmaf(v0, w.x, acc1);
            acc1 = fmaf(v1, w.y, acc1);
            acc2 = fmaf(v0, w.z, acc2);
            acc2 = fmaf(v1, w.w, acc2);
        }
        float h = tanhf(acc1) * (1.0f / (1.0f + expf(-acc2)));

        float acc = 0.0f;
        #pragma unroll
        for (int dc = 0; dc < 32; ++dc) {
            float hv = __shfl_sync(0xffffffffu, h, dc);
            acc = fmaf(hv, gsh[dc][lane], acc);
        }
        d_hw[(size_t)task * NC + lane] = acc;   // bt-major
    }
}

// ---------------- CSR gather: one warp per (n, bt-pair); 2 bt slices per warp ----------------
__global__ void __launch_bounds__(256) k_gather(
    const float* __restrict__ gb, float* __restrict__ out)
{
    int tid = threadIdx.x;
    int lane = tid & 31, wid = tid >> 5;
    float bias = gb[lane];
    int nwarps = gridDim.x * 8;
    const int NTASK = (BT / 2) * NN;   // 128000

    for (int task = blockIdx.x * 8 + wid; task < NTASK; task += nwarps) {
        int n  = task >> 6;            // consecutive tasks share n -> CSR row reuse
        int bp = task & 63;
        const float* h0 = d_hw + ((size_t)(2 * bp    ) * NN) * NC;
        const float* h1 = d_hw + ((size_t)(2 * bp + 1) * NN) * NC;
        float sn = d_selfnorm[n];
        float acc0 = sn * h0[n * NC + lane];
        float acc1 = sn * h1[n * NC + lane];
        int s = d_start[n], e = d_start[n + 1];
        #pragma unroll 2
        for (int k = s; k < e; ++k) {
            int   src = __ldg(&d_src[k]);
            float w   = __ldg(&d_cnorm[k]);
            int off = src * NC + lane;
            acc0 = fmaf(w, h0[off], acc0);
            acc1 = fmaf(w, h1[off], acc1);
        }
        out[((size_t)(2 * bp    ) * NN + n) * NC + lane] = acc0 + bias;
        out[((size_t)(2 * bp + 1) * NN + n) * NC + lane] = acc1 + bias;
    }
}

// ---------------- launch (gate first: independent of CSR setup; puts gather at -s 5) ----------------
extern "C" void kernel_launch(void* const* d_in, const int* in_sizes, int n_in,
                              void* d_out, int out_size)
{
    const float* x   = (const float*)d_in[0];
    const int*   ei  = (const int*)d_in[1];
    const float* ew  = (const float*)d_in[2];
    const float* g1w = (const float*)d_in[3];
    const float* g1b = (const float*)d_in[4];
    const float* g2w = (const float*)d_in[5];
    const float* g2b = (const float*)d_in[6];
    const float* gw  = (const float*)d_in[7];
    const float* gb  = (const float*)d_in[8];
    float* out = (float*)d_out;

    k_gate<<<1184, 256>>>(x, g1w, g1b, g2w, g2b, gw);   // launch 0
    k_setup1<<<(NN + 255) / 256, 256>>>(ei);            // launch 1
    k_count<<<(NE + 255) / 256, 256>>>(ei, ew);         // launch 2
    k_scan<<<1, 1024>>>();                              // launch 3
    k_fill<<<(NE + 255) / 256, 256>>>(ei, ew);          // launch 4
    k_gather<<<1184, 256>>>(gb, out);                   // launch 5  <- ncu -s 5
}

// round 7
// speedup vs baseline: 1.5392x; 1.0596x over previous
#include <cuda_runtime.h>

#define NN 2000
#define NE 40000
#define NB 4
#define NT 34
#define TP 32
#define BT 128          // NB * TP
#define NC 32           // channels (C_IN == DC == 32)

// ---------------- device scratch (static, no runtime alloc) ----------------
__device__ float d_hw[BT * NN * NC];     // (bt, n, ch)  bt-major
__device__ float d_deg[NN];
__device__ float d_dis[NN];
__device__ float d_selfnorm[NN];
__device__ int   d_cnt[NN];
__device__ int   d_start[NN + 1];
__device__ int   d_cursor[NN];
__device__ int   d_src[NE];
__device__ float d_cnorm[NE];
__device__ int   d_is64;                 // edge_index stored as int64?

__device__ __forceinline__ int edge_at(const int* __restrict__ ei, int idx) {
    return d_is64 ? ei[2 * idx] : ei[idx];
}

// ---------------- setup: dtype detect + init ----------------
__global__ void k_setup1(const int* __restrict__ ei) {
    int n = blockIdx.x * blockDim.x + threadIdx.x;
    if (n < NN) { d_deg[n] = 1.0f; d_cnt[n] = 0; }   // self-loop weight = 1
    if (blockIdx.x == 0 && threadIdx.x < 32) {
        int lane = threadIdx.x;
        int nz = 0;
        for (int i = lane; i < 128; i += 32)
            if (ei[2 * i + 1] != 0) nz = 1;
        unsigned any = __ballot_sync(0xffffffffu, nz);
        if (lane == 0) d_is64 = (any == 0u) ? 1 : 0;
    }
}

__global__ void k_count(const int* __restrict__ ei,
                        const float* __restrict__ ew) {
    int e = blockIdx.x * blockDim.x + threadIdx.x;
    if (e < NE) {
        int col = edge_at(ei, NE + e);
        atomicAdd(&d_deg[col], ew[e]);
        atomicAdd(&d_cnt[col], 1);
    }
}

// scan over d_cnt -> d_start/d_cursor; also deg -> dis/selfnorm (fused)
__global__ void k_scan() {
    __shared__ int sh[1024];
    int t = threadIdx.x;
    int i0 = 2 * t, i1 = 2 * t + 1;
    if (i0 < NN) { float r = rsqrtf(d_deg[i0]); d_dis[i0] = r; d_selfnorm[i0] = r * r; }
    if (i1 < NN) { float r = rsqrtf(d_deg[i1]); d_dis[i1] = r; d_selfnorm[i1] = r * r; }
    int a = (i0 < NN) ? d_cnt[i0] : 0;
    int b = (i1 < NN) ? d_cnt[i1] : 0;
    int s = a + b;
    sh[t] = s;
    __syncthreads();
    for (int off = 1; off < 1024; off <<= 1) {
        int v = (t >= off) ? sh[t - off] : 0;
        __syncthreads();
        sh[t] += v;
        __syncthreads();
    }
    int excl = sh[t] - s;
    if (i0 < NN) { d_start[i0] = excl;     d_cursor[i0] = excl; }
    if (i1 < NN) { d_start[i1] = excl + a; d_cursor[i1] = excl + a; }
    if (t == 1023) d_start[NN] = sh[1023];
}

__global__ void k_fill(const int* __restrict__ ei,
                       const float* __restrict__ ew) {
    int e = blockIdx.x * blockDim.x + threadIdx.x;
    if (e < NE) {
        int row = edge_at(ei, e);
        int col = edge_at(ei, NE + e);
        float nw = d_dis[row] * ew[e] * d_dis[col];
        int pos = atomicAdd(&d_cursor[col], 1);
        d_src[pos]   = row;
        d_cnorm[pos] = nw;
    }
}

// ---------------- gate conv + tanh*sigmoid + gcn_w GEMM ----------------
// one warp per (bt, n); lane = channel. writes bt-major (bt, n, ch).
__global__ void __launch_bounds__(256) k_gate(
    const float* __restrict__ x,
    const float* __restrict__ g1w, const float* __restrict__ g1b,
    const float* __restrict__ g2w, const float* __restrict__ g2b,
    const float* __restrict__ gw)
{
    __shared__ float4 wpack[32][32];   // [c][dc] = (w1a, w1b, w2a, w2b)
    __shared__ float  gsh[32][32];     // [dc][ch]
    int tid = threadIdx.x;
    for (int i = tid; i < 1024; i += 256) {
        int dc = i & 31, c = i >> 5;
        wpack[c][dc] = make_float4(g1w[dc * 64 + c * 2], g1w[dc * 64 + c * 2 + 1],
                                   g2w[dc * 64 + c * 2], g2w[dc * 64 + c * 2 + 1]);
        gsh[i >> 5][i & 31] = gw[i];   // gw[dc*32 + ch]
    }
    __syncthreads();

    int lane = tid & 31, wid = tid >> 5;
    float b1 = g1b[lane], b2 = g2b[lane];
    int nwarps = gridDim.x * 8;

    for (int task = blockIdx.x * 8 + wid; task < BT * NN; task += nwarps) {
        int bt = task / NN;
        int n  = task - bt * NN;
        int b  = bt >> 5, t = bt & 31;
        const float* xp = x + (((size_t)b * NT + t) * NN + n) * NC;
        float x0 = xp[lane];
        float x1 = xp[2 * NN * NC + lane];

        float acc1 = b1, acc2 = b2;
        #pragma unroll
        for (int c = 0; c < 32; ++c) {
            float v0 = __shfl_sync(0xffffffffu, x0, c);
            float v1 = __shfl_sync(0xffffffffu, x1, c);
            float4 w = wpack[c][lane];
            acc1 = fmaf(v0, w.x, acc1);
            acc1 = fmaf(v1, w.y, acc1);
            acc2 = fmaf(v0, w.z, acc2);
            acc2 = fmaf(v1, w.w, acc2);
        }
        float h = tanhf(acc1) * (1.0f / (1.0f + expf(-acc2)));

        float acc = 0.0f;
        #pragma unroll
        for (int dc = 0; dc < 32; ++dc) {
            float hv = __shfl_sync(0xffffffffu, h, dc);
            acc = fmaf(hv, gsh[dc][lane], acc);
        }
        d_hw[(size_t)task * NC + lane] = acc;   // bt-major
    }
}

// ---------------- CSR gather: one warp per (n, bt-quad); 4 bt slices per warp ----------------
__global__ void __launch_bounds__(256) k_gather(
    const float* __restrict__ gb, float* __restrict__ out)
{
    int tid = threadIdx.x;
    int lane = tid & 31, wid = tid >> 5;
    float bias = gb[lane];
    int nwarps = gridDim.x * 8;
    const int NTASK = (BT / 4) * NN;   // 64000

    for (int task = blockIdx.x * 8 + wid; task < NTASK; task += nwarps) {
        int n = task >> 5;             // 32 consecutive tasks share n -> CSR reuse in L1
        int q = task & 31;
        const int stride = NN * NC;
        const float* h0 = d_hw + (size_t)(4 * q    ) * stride;
        const float* h1 = h0 + stride;
        const float* h2 = h1 + stride;
        const float* h3 = h2 + stride;
        int own = n * NC + lane;
        float sn = d_selfnorm[n];
        float acc0 = sn * h0[own];
        float acc1 = sn * h1[own];
        float acc2 = sn * h2[own];
        float acc3 = sn * h3[own];
        int s = d_start[n], e = d_start[n + 1];
        #pragma unroll 2
        for (int k = s; k < e; ++k) {
            int   src = __ldg(&d_src[k]);
            float w   = __ldg(&d_cnorm[k]);
            int off = src * NC + lane;
            acc0 = fmaf(w, h0[off], acc0);
            acc1 = fmaf(w, h1[off], acc1);
            acc2 = fmaf(w, h2[off], acc2);
            acc3 = fmaf(w, h3[off], acc3);
        }
        float* o = out + ((size_t)(4 * q) * NN + n) * NC + lane;
        o[0]          = acc0 + bias;
        o[stride]     = acc1 + bias;
        o[2 * stride] = acc2 + bias;
        o[3 * stride] = acc3 + bias;
    }
}

// ---------------- launch (gate at index 3: ncu window lands there) ----------------
extern "C" void kernel_launch(void* const* d_in, const int* in_sizes, int n_in,
                              void* d_out, int out_size)
{
    const float* x   = (const float*)d_in[0];
    const int*   ei  = (const int*)d_in[1];
    const float* ew  = (const float*)d_in[2];
    const float* g1w = (const float*)d_in[3];
    const float* g1b = (const float*)d_in[4];
    const float* g2w = (const float*)d_in[5];
    const float* g2b = (const float*)d_in[6];
    const float* gw  = (const float*)d_in[7];
    const float* gb  = (const float*)d_in[8];
    float* out = (float*)d_out;

    k_setup1<<<(NN + 255) / 256, 256>>>(ei);            // 0
    k_count<<<(NE + 255) / 256, 256>>>(ei, ew);         // 1
    k_scan<<<1, 1024>>>();                              // 2
    k_gate<<<1184, 256>>>(x, g1w, g1b, g2w, g2b, gw);   // 3  <- profiled
    k_fill<<<(NE + 255) / 256, 256>>>(ei, ew);          // 4
    k_gather<<<1184, 256>>>(gb, out);                   // 5
}

// round 13
// speedup vs baseline: 2.2870x; 1.4858x over previous
#include <cuda_runtime.h>

#define NN 2000
#define NE 40000
#define NB 4
#define NT 34
#define TP 32
#define BT 128          // NB * TP
#define NC 32           // channels (C_IN == DC == 32)
#define TM 64           // tile rows (n per block) in k_gate
#define NTILE 32        // ceil(NN / TM) = 32 (last tile partial: 16 rows)

// ---------------- device scratch (static, no runtime alloc) ----------------
__device__ float d_hw[BT * NN * NC];     // (bt, n, ch)  bt-major
__device__ float d_deg[NN];
__device__ float d_dis[NN];
__device__ float d_selfnorm[NN];
__device__ int   d_cnt[NN];
__device__ int   d_start[NN + 1];
__device__ int   d_cursor[NN];
__device__ int   d_src[NE];
__device__ float d_cnorm[NE];
__device__ int   d_is64;                 // edge_index stored as int64?

__device__ __forceinline__ int edge_at(const int* __restrict__ ei, int idx) {
    return d_is64 ? ei[2 * idx] : ei[idx];
}

// ---------------- setup: dtype detect + init ----------------
__global__ void k_setup1(const int* __restrict__ ei) {
    int n = blockIdx.x * blockDim.x + threadIdx.x;
    if (n < NN) { d_deg[n] = 1.0f; d_cnt[n] = 0; }   // self-loop weight = 1
    if (blockIdx.x == 0 && threadIdx.x < 32) {
        int lane = threadIdx.x;
        int nz = 0;
        for (int i = lane; i < 128; i += 32)
            if (ei[2 * i + 1] != 0) nz = 1;
        unsigned any = __ballot_sync(0xffffffffu, nz);
        if (lane == 0) d_is64 = (any == 0u) ? 1 : 0;
    }
}

__global__ void k_count(const int* __restrict__ ei,
                        const float* __restrict__ ew) {
    int e = blockIdx.x * blockDim.x + threadIdx.x;
    if (e < NE) {
        int col = edge_at(ei, NE + e);
        atomicAdd(&d_deg[col], ew[e]);
        atomicAdd(&d_cnt[col], 1);
    }
}

// scan over d_cnt -> d_start/d_cursor; also deg -> dis/selfnorm (fused)
__global__ void k_scan() {
    __shared__ int sh[1024];
    int t = threadIdx.x;
    int i0 = 2 * t, i1 = 2 * t + 1;
    if (i0 < NN) { float r = rsqrtf(d_deg[i0]); d_dis[i0] = r; d_selfnorm[i0] = r * r; }
    if (i1 < NN) { float r = rsqrtf(d_deg[i1]); d_dis[i1] = r; d_selfnorm[i1] = r * r; }
    int a = (i0 < NN) ? d_cnt[i0] : 0;
    int b = (i1 < NN) ? d_cnt[i1] : 0;
    int s = a + b;
    sh[t] = s;
    __syncthreads();
    for (int off = 1; off < 1024; off <<= 1) {
        int v = (t >= off) ? sh[t - off] : 0;
        __syncthreads();
        sh[t] += v;
        __syncthreads();
    }
    int excl = sh[t] - s;
    if (i0 < NN) { d_start[i0] = excl;     d_cursor[i0] = excl; }
    if (i1 < NN) { d_start[i1] = excl + a; d_cursor[i1] = excl + a; }
    if (t == 1023) d_start[NN] = sh[1023];
}

__global__ void k_fill(const int* __restrict__ ei,
                       const float* __restrict__ ew) {
    int e = blockIdx.x * blockDim.x + threadIdx.x;
    if (e < NE) {
        int row = edge_at(ei, e);
        int col = edge_at(ei, NE + e);
        float nw = d_dis[row] * ew[e] * d_dis[col];
        int pos = atomicAdd(&d_cursor[col], 1);
        d_src[pos]   = row;
        d_cnorm[pos] = nw;
    }
}

// ---------------- gate: tile-GEMM, broadcast weights, no shuffles ----------------
// block = one tile of TM=64 rows (consecutive n, same bt). 256 threads.
// stage1: H[m][dc] = tanh(conv1) * sigmoid(conv2);  stage2: hw[m][ch] = H·gcn_w
__global__ void __launch_bounds__(256) k_gate(
    const float* __restrict__ x,
    const float* __restrict__ g1w, const float* __restrict__ g1b,
    const float* __restrict__ g2w, const float* __restrict__ g2b,
    const float* __restrict__ gw)
{
    __shared__ float  X0[TM * 33];       // [m][c] stride 33 (conflict-free both ways)
    __shared__ float  X1[TM * 33];
    __shared__ float  H [TM * 33];
    __shared__ float4 wpack[32][32];     // [c][dc] = (w1a, w1b, w2a, w2b)
    __shared__ float4 gsh4[32 * 8];      // [dc][ch/4] row chunks of gcn_w

    int tid  = threadIdx.x;
    int lane = tid & 31;                 // m_lane
    int wg   = tid >> 5;                 // warp id 0..7
    int bt   = blockIdx.x >> 5;          // 0..127
    int n0   = (blockIdx.x & 31) * TM;   // 0..1984
    int b    = bt >> 5, t = bt & 31;

    // weights -> shared (broadcast-friendly forms)
    for (int i = tid; i < 1024; i += 256) {
        int dc = i & 31, c = i >> 5;
        wpack[c][dc] = make_float4(g1w[dc * 64 + c * 2], g1w[dc * 64 + c * 2 + 1],
                                   g2w[dc * 64 + c * 2], g2w[dc * 64 + c * 2 + 1]);
    }
    for (int i = tid; i < 256; i += 256)
        gsh4[i] = ((const float4*)gw)[i];       // gw[dc][ch] row-major

    // x slab -> shared, transposed-padded. slab is contiguous 2048 floats per tap.
    const float* p0 = x + ((size_t)(b * NT + t)) * NN * NC + (size_t)n0 * NC;
    const float* p1 = p0 + 2 * NN * NC;
    for (int i = tid; i < TM * NC; i += 256) {
        int m = i >> 5, c = i & 31;
        bool ok = (n0 + m) < NN;
        X0[m * 33 + c] = ok ? p0[i] : 0.0f;
        X1[m * 33 + c] = ok ? p1[i] : 0.0f;
    }
    __syncthreads();

    // ---- stage 1: gates for 2 m-rows (lane, lane+32) x 4 dc (wg*4..wg*4+3) ----
    int dc0 = wg * 4;
    float acc1[2][4], acc2[2][4];
    #pragma unroll
    for (int j = 0; j < 4; ++j) {
        float bb1 = g1b[dc0 + j], bb2 = g2b[dc0 + j];
        acc1[0][j] = bb1; acc1[1][j] = bb1;
        acc2[0][j] = bb2; acc2[1][j] = bb2;
    }
    #pragma unroll 4
    for (int c = 0; c < 32; ++c) {
        float xa0 = X0[lane * 33 + c];
        float xa1 = X1[lane * 33 + c];
        float xb0 = X0[(lane + 32) * 33 + c];
        float xb1 = X1[(lane + 32) * 33 + c];
        #pragma unroll
        for (int j = 0; j < 4; ++j) {
            float4 w = wpack[c][dc0 + j];
            acc1[0][j] = fmaf(xa1, w.y, fmaf(xa0, w.x, acc1[0][j]));
            acc2[0][j] = fmaf(xa1, w.w, fmaf(xa0, w.z, acc2[0][j]));
            acc1[1][j] = fmaf(xb1, w.y, fmaf(xb0, w.x, acc1[1][j]));
            acc2[1][j] = fmaf(xb1, w.w, fmaf(xb0, w.z, acc2[1][j]));
        }
    }
    #pragma unroll
    for (int i = 0; i < 2; ++i)
        #pragma unroll
        for (int j = 0; j < 4; ++j) {
            float h = tanhf(acc1[i][j]) * (1.0f / (1.0f + expf(-acc2[i][j])));
            H[(lane + 32 * i) * 33 + dc0 + j] = h;
        }
    __syncthreads();

    // ---- stage 2: hw[m][ch] = H[m][:] . gcn_w[:, ch], ch block = wg*4..+3 ----
    float acc[2][4] = {};
    #pragma unroll 4
    for (int dc = 0; dc < 32; ++dc) {
        float ha = H[lane * 33 + dc];
        float hb = H[(lane + 32) * 33 + dc];
        float4 g = gsh4[dc * 8 + wg];
        acc[0][0] = fmaf(ha, g.x, acc[0][0]);
        acc[0][1] = fmaf(ha, g.y, acc[0][1]);
        acc[0][2] = fmaf(ha, g.z, acc[0][2]);
        acc[0][3] = fmaf(ha, g.w, acc[0][3]);
        acc[1][0] = fmaf(hb, g.x, acc[1][0]);
        acc[1][1] = fmaf(hb, g.y, acc[1][1]);
        acc[1][2] = fmaf(hb, g.z, acc[1][2]);
        acc[1][3] = fmaf(hb, g.w, acc[1][3]);
    }
    // store (bias added in gather)
    #pragma unroll
    for (int i = 0; i < 2; ++i) {
        int n = n0 + lane + 32 * i;
        if (n < NN) {
            float4 v = make_float4(acc[i][0], acc[i][1], acc[i][2], acc[i][3]);
            *(float4*)(d_hw + ((size_t)bt * NN + n) * NC + wg * 4) = v;
        }
    }
}

// ---------------- CSR gather: one warp per (n, bt-quad); 4 bt slices per warp ----------------
__global__ void __launch_bounds__(256) k_gather(
    const float* __restrict__ gb, float* __restrict__ out)
{
    int tid = threadIdx.x;
    int lane = tid & 31, wid = tid >> 5;
    float bias = gb[lane];
    int nwarps = gridDim.x * 8;
    const int NTASK = (BT / 4) * NN;   // 64000

    for (int task = blockIdx.x * 8 + wid; task < NTASK; task += nwarps) {
        int n = task >> 5;             // 32 consecutive tasks share n -> CSR reuse in L1
        int q = task & 31;
        const int stride = NN * NC;
        const float* h0 = d_hw + (size_t)(4 * q    ) * stride;
        const float* h1 = h0 + stride;
        const float* h2 = h1 + stride;
        const float* h3 = h2 + stride;
        int own = n * NC + lane;
        float sn = d_selfnorm[n];
        float acc0 = sn * h0[own];
        float acc1 = sn * h1[own];
        float acc2 = sn * h2[own];
        float acc3 = sn * h3[own];
        int s = d_start[n], e = d_start[n + 1];
        #pragma unroll 2
        for (int k = s; k < e; ++k) {
            int   src = __ldg(&d_src[k]);
            float w   = __ldg(&d_cnorm[k]);
            int off = src * NC + lane;
            acc0 = fmaf(w, h0[off], acc0);
            acc1 = fmaf(w, h1[off], acc1);
            acc2 = fmaf(w, h2[off], acc2);
            acc3 = fmaf(w, h3[off], acc3);
        }
        float* o = out + ((size_t)(4 * q) * NN + n) * NC + lane;
        o[0]          = acc0 + bias;
        o[stride]     = acc1 + bias;
        o[2 * stride] = acc2 + bias;
        o[3 * stride] = acc3 + bias;
    }
}

// ---------------- launch (gate at index 3: ncu window lands there) ----------------
extern "C" void kernel_launch(void* const* d_in, const int* in_sizes, int n_in,
                              void* d_out, int out_size)
{
    const float* x   = (const float*)d_in[0];
    const int*   ei  = (const int*)d_in[1];
    const float* ew  = (const float*)d_in[2];
    const float* g1w = (const float*)d_in[3];
    const float* g1b = (const float*)d_in[4];
    const float* g2w = (const float*)d_in[5];
    const float* g2b = (const float*)d_in[6];
    const float* gw  = (const float*)d_in[7];
    const float* gb  = (const float*)d_in[8];
    float* out = (float*)d_out;

    k_setup1<<<(NN + 255) / 256, 256>>>(ei);            // 0
    k_count<<<(NE + 255) / 256, 256>>>(ei, ew);         // 1
    k_scan<<<1, 1024>>>();                              // 2
    k_gate<<<BT * NTILE, 256>>>(x, g1w, g1b, g2w, g2b, gw);  // 3  <- profiled (4096 blocks)
    k_fill<<<(NE + 255) / 256, 256>>>(ei, ew);          // 4
    k_gather<<<1184, 256>>>(gb, out);                   // 5
}